// round 6
// baseline (speedup 1.0000x reference)
#include <cuda_runtime.h>
#include <cstdint>

#define NN 256
#define DD 768
#define EE 768
#define FF 96
#define HH 8
#define LL 2
#define ALPHAV 0.2f
#define NEGV (-9000000000000000.0f)

typedef unsigned long long ull;

static __device__ __forceinline__ void ffma2(ull &d, ull a, ull b) {
    asm("fma.rn.f32x2 %0, %1, %2, %0;" : "+l"(d) : "l"(a), "l"(b));
}
static __device__ __forceinline__ float2 unpack2(ull v) {
    float2 r; asm("mov.b64 {%0, %1}, %2;" : "=f"(r.x), "=f"(r.y) : "l"(v)); return r;
}

// ---------------- device scratch ----------------
__device__ float g_wk_a2[LL*HH*EE];
__device__ float g_se[(size_t)LL*HH*NN*NN];
__device__ float g_hq[HH*NN*FF];
__device__ float g_hk[HH*NN*FF];
__device__ float g_hv[HH*NN*FF];
__device__ float g_sq[HH*NN];
__device__ float g_sk[HH*NN];
__device__ float g_att[HH*NN*NN];
__device__ __align__(16) float g_ec[HH*NN*EE];
__device__ float g_cur[NN*DD];

// ---------------- K0: copy x into out[:, 0:768] ----------------
__global__ void k_copy_x(const float* __restrict__ x, float* __restrict__ out) {
    int idx = blockIdx.x*blockDim.x + threadIdx.x;
    if (idx >= NN*DD) return;
    int n = idx / DD, c = idx - n*DD;
    out[(size_t)n*(3*DD) + c] = x[idx];
}

// ---------------- K1: wk_a2 ----------------
__global__ void k_wk_a2(const float* __restrict__ Wk, const float* __restrict__ a) {
    int gw   = (blockIdx.x*blockDim.x + threadIdx.x) >> 5;
    int lane = threadIdx.x & 31;
    if (gw >= LL*HH*EE) return;
    int lh = gw / EE;
    int d  = gw - lh*EE;
    const float* wrow = Wk + ((size_t)lh*(DD+EE) + DD + d)*FF;
    const float* arow = a + (size_t)lh*2*FF + FF;
    float s = 0.f;
    #pragma unroll
    for (int p = 0; p < 3; p++) s += wrow[lane + p*32] * arow[lane + p*32];
    #pragma unroll
    for (int o = 16; o; o >>= 1) s += __shfl_xor_sync(0xffffffffu, s, o);
    if (lane == 0) g_wk_a2[gw] = s;
}

// ---------------- K2: s_e = e_flat(65536x768) @ wk_a2^T(768x16) ----------------
// 512 blocks x 128 rows, 128 threads. FFMA2: thread = 4 rows x 4 cols.
__global__ __launch_bounds__(128) void k_se(const float* __restrict__ e) {
    __shared__ __align__(16) float As[32][132];   // [k][row], stride 528B (16B mult)
    __shared__ __align__(16) float Bd[32][34];    // [k][2*col] duplicated
    int t  = threadIdx.x;
    int r0 = blockIdx.x * 128;
    int rg4 = (t & 31) * 4;         // 4 rows per thread
    int c0  = (t >> 5) * 4;         // 4 cols per thread
    int ar = t >> 3, ak = (t & 7) * 4;   // A load: rows ar + p*16, k = ak..ak+3

    ull acc[2][4];
    #pragma unroll
    for (int p = 0; p < 2; p++)
        #pragma unroll
        for (int c = 0; c < 4; c++) acc[p][c] = 0ull;

    float4 pa[8];
    float  pbv[4];
    #pragma unroll
    for (int p = 0; p < 8; p++)
        pa[p] = *(const float4*)(e + (size_t)(r0 + ar + p*16)*EE + ak);
    #pragma unroll
    for (int p = 0; p < 4; p++) {
        int idx = t + p*128;
        pbv[p] = g_wk_a2[(idx >> 5)*EE + (idx & 31)];
    }

    for (int kt = 0; kt < 24; kt++) {
        #pragma unroll
        for (int p = 0; p < 8; p++) {
            int r = ar + p*16;
            As[ak+0][r] = pa[p].x; As[ak+1][r] = pa[p].y;
            As[ak+2][r] = pa[p].z; As[ak+3][r] = pa[p].w;
        }
        #pragma unroll
        for (int p = 0; p < 4; p++) {
            int idx = t + p*128;
            float v = pbv[p];
            *(float2*)&Bd[idx & 31][2*(idx >> 5)] = make_float2(v, v);
        }
        __syncthreads();
        if (kt < 23) {
            int k0 = (kt+1)*32;
            #pragma unroll
            for (int p = 0; p < 8; p++)
                pa[p] = *(const float4*)(e + (size_t)(r0 + ar + p*16)*EE + k0 + ak);
            #pragma unroll
            for (int p = 0; p < 4; p++) {
                int idx = t + p*128;
                pbv[p] = g_wk_a2[(idx >> 5)*EE + k0 + (idx & 31)];
            }
        }
        #pragma unroll
        for (int k = 0; k < 32; k++) {
            ulonglong2 av = *(const ulonglong2*)&As[k][rg4];
            #pragma unroll
            for (int cc = 0; cc < 4; cc++) {
                ull b = *(const ull*)&Bd[k][2*(c0+cc)];
                ffma2(acc[0][cc], av.x, b);
                ffma2(acc[1][cc], av.y, b);
            }
        }
        __syncthreads();
    }
    #pragma unroll
    for (int cc = 0; cc < 4; cc++) {
        int c = c0 + cc;
        #pragma unroll
        for (int p = 0; p < 2; p++) {
            float2 u = unpack2(acc[p][cc]);
            g_se[(size_t)c*65536 + r0 + rg4 + p*2 + 0] = u.x;
            g_se[(size_t)c*65536 + r0 + rg4 + p*2 + 1] = u.y;
        }
    }
}

// ---------------- K3: projections, per-(mat,h) blocks, FFMA2, fused sq/sk ----------------
// grid (24, 8): mat = sel*8+h, row tile 32. 256 threads: 8 row-groups x 32 col-lanes.
__global__ __launch_bounds__(256) void k_proj(const float* __restrict__ x,
                                              const float* __restrict__ Wq,
                                              const float* __restrict__ Wk,
                                              const float* __restrict__ Wv,
                                              const float* __restrict__ a, int l) {
    const float* cur = l ? g_cur : x;
    int m = blockIdx.x, sel = m >> 3, h = m & 7;
    int lh = l*8 + h;
    int R0 = blockIdx.y * 32;
    const float* W = (sel == 0) ? Wq + (size_t)lh*DD*FF
                   : (sel == 1) ? Wk + (size_t)lh*(DD+EE)*FF
                   :              Wv + (size_t)lh*(DD+EE)*FF;
    __shared__ __align__(16) float As[32][36];     // [k][row], 144B rows
    __shared__ __align__(16) float Bs[32][192];    // [k][2*f] duplicated

    int t = threadIdx.x;
    int ar = t >> 3, ak = (t & 7)*4;
    int bks[3], bfs[3];
    #pragma unroll
    for (int p = 0; p < 3; p++) { int idx = t + p*256; bks[p] = idx/24; bfs[p] = (idx - bks[p]*24)*4; }
    int ty = t >> 5, fx = t & 31;

    ull acc[2][3];
    #pragma unroll
    for (int p = 0; p < 2; p++)
        #pragma unroll
        for (int c = 0; c < 3; c++) acc[p][c] = 0ull;

    const float* ap = cur + (size_t)(R0 + ar)*DD + ak;
    float4 pa = *(const float4*)ap;
    float4 pb[3];
    #pragma unroll
    for (int p = 0; p < 3; p++)
        pb[p] = *(const float4*)(W + (size_t)bks[p]*FF + bfs[p]);

    for (int kt = 0; kt < 24; kt++) {
        As[ak+0][ar] = pa.x; As[ak+1][ar] = pa.y; As[ak+2][ar] = pa.z; As[ak+3][ar] = pa.w;
        #pragma unroll
        for (int p = 0; p < 3; p++) {
            float2* d = (float2*)&Bs[bks[p]][2*bfs[p]];
            d[0] = make_float2(pb[p].x, pb[p].x);
            d[1] = make_float2(pb[p].y, pb[p].y);
            d[2] = make_float2(pb[p].z, pb[p].z);
            d[3] = make_float2(pb[p].w, pb[p].w);
        }
        __syncthreads();
        if (kt < 23) {
            int k0 = (kt+1)*32;
            pa = *(const float4*)(ap + k0);
            #pragma unroll
            for (int p = 0; p < 3; p++)
                pb[p] = *(const float4*)(W + (size_t)(k0 + bks[p])*FF + bfs[p]);
        }
        #pragma unroll
        for (int k = 0; k < 32; k++) {
            ulonglong2 av = *(const ulonglong2*)&As[k][ty*4];
            ull b0 = *(const ull*)&Bs[k][2*fx];
            ull b1 = *(const ull*)&Bs[k][2*(fx+32)];
            ull b2 = *(const ull*)&Bs[k][2*(fx+64)];
            ffma2(acc[0][0], av.x, b0); ffma2(acc[0][1], av.x, b1); ffma2(acc[0][2], av.x, b2);
            ffma2(acc[1][0], av.y, b0); ffma2(acc[1][1], av.y, b1); ffma2(acc[1][2], av.y, b2);
        }
        __syncthreads();
    }

    float accf[4][3];
    #pragma unroll
    for (int c = 0; c < 3; c++) {
        float2 u0 = unpack2(acc[0][c]); accf[0][c] = u0.x; accf[1][c] = u0.y;
        float2 u1 = unpack2(acc[1][c]); accf[2][c] = u1.x; accf[3][c] = u1.y;
    }
    float* dst = (sel == 0) ? g_hq : (sel == 1) ? g_hk : g_hv;
    #pragma unroll
    for (int rr = 0; rr < 4; rr++) {
        int n = R0 + ty*4 + rr;
        #pragma unroll
        for (int c = 0; c < 3; c++)
            dst[((size_t)h*NN + n)*FF + fx + c*32] = accf[rr][c];
    }
    if (sel < 2) {      // fused sq / sk
        const float* av = a + (size_t)lh*2*FF + sel*FF;
        float a0 = av[fx], a1 = av[fx+32], a2 = av[fx+64];
        #pragma unroll
        for (int rr = 0; rr < 4; rr++) {
            float p = accf[rr][0]*a0 + accf[rr][1]*a1 + accf[rr][2]*a2;
            #pragma unroll
            for (int o = 16; o; o >>= 1) p += __shfl_xor_sync(0xffffffffu, p, o);
            if (fx == 0)
                (sel ? g_sk : g_sq)[h*NN + R0 + ty*4 + rr] = p;
        }
    }
}

// ---------------- K5: softmax ----------------
__global__ __launch_bounds__(256) void k_softmax(const int* __restrict__ adj, int l) {
    int i = blockIdx.x, h = blockIdx.y, j = threadIdx.x;
    int lh = l*8 + h;
    float sv = g_sq[h*NN + i] + g_sk[h*NN + j] + g_se[((size_t)lh*NN + i)*NN + j];
    sv = sv > 0.f ? sv : ALPHAV*sv;
    if (adj[i*NN + j] <= 0) sv = NEGV;

    __shared__ float red[8];
    int lane = j & 31, wid = j >> 5;
    float m = sv;
    #pragma unroll
    for (int o = 16; o; o >>= 1) m = fmaxf(m, __shfl_xor_sync(0xffffffffu, m, o));
    if (lane == 0) red[wid] = m;
    __syncthreads();
    float mx = red[0];
    #pragma unroll
    for (int p = 1; p < 8; p++) mx = fmaxf(mx, red[p]);
    __syncthreads();

    float ex = __expf(sv - mx);
    float s = ex;
    #pragma unroll
    for (int o = 16; o; o >>= 1) s += __shfl_xor_sync(0xffffffffu, s, o);
    if (lane == 0) red[wid] = s;
    __syncthreads();
    float tot = red[0];
    #pragma unroll
    for (int p = 1; p < 8; p++) tot += red[p];
    g_att[((size_t)h*NN + i)*NN + j] = ex * (1.0f / tot);
}

// ---------------- K6: ec[h,i,d] = sum_j att[h,i,j]*e[i,j,d], FFMA2 + dup att ----------------
__global__ __launch_bounds__(96) void k_ec(const float* __restrict__ e) {
    int i = blockIdx.x;
    int t = threadIdx.x;
    __shared__ __align__(16) float sattd[HH*NN*2];   // duplicated: 16KB
    for (int idx = t; idx < HH*NN; idx += 96) {
        float v = g_att[(size_t)(idx >> 8)*NN*NN + (size_t)i*NN + (idx & 255)];
        *(float2*)&sattd[(idx >> 8)*512 + 2*(idx & 255)] = make_float2(v, v);
    }
    __syncthreads();

    int d0 = blockIdx.y*384 + t*4;
    ull acc[8][2];
    #pragma unroll
    for (int h = 0; h < 8; h++) { acc[h][0] = 0ull; acc[h][1] = 0ull; }
    const float* ebase = e + (size_t)i*NN*EE + d0;
    #pragma unroll 1
    for (int j = 0; j < NN; j += 8) {
        ulonglong2 ev[8];
        #pragma unroll
        for (int u = 0; u < 8; u++)
            ev[u] = *(const ulonglong2*)(ebase + (size_t)(j+u)*EE);
        #pragma unroll
        for (int h = 0; h < 8; h++) {
            #pragma unroll
            for (int u = 0; u < 8; u++) {
                ull av = *(const ull*)&sattd[h*512 + 2*(j+u)];
                ffma2(acc[h][0], av, ev[u].x);
                ffma2(acc[h][1], av, ev[u].y);
            }
        }
    }
    #pragma unroll
    for (int h = 0; h < 8; h++) {
        ulonglong2 o; o.x = acc[h][0]; o.y = acc[h][1];
        *(ulonglong2*)(g_ec + ((size_t)(h*NN + i))*EE + d0) = o;
    }
}

// ---------------- K7: out = [att|ec] @ [hv;Wv_e], ELU. FFMA2 + dup B ----------------
// grid (16, 8), 128 threads. Tile 16 rows x 96 cols; thread = 4 rows x 3 cols.
__global__ __launch_bounds__(128) void k_av(const float* __restrict__ Wv,
                                            float* __restrict__ out, int l) {
    __shared__ __align__(16) float Aat[32][20];    // [k][row], 80B rows
    __shared__ __align__(16) float Bvd[32][192];   // [k][2*f] duplicated
    int t  = threadIdx.x;
    int I0 = blockIdx.x*16, h = blockIdx.y;
    int ty = t >> 5, fx = t & 31;
    const float* Wve = Wv + ((size_t)(l*8+h)*(DD+EE) + DD)*FF;

    ull acc[2][3];
    #pragma unroll
    for (int p = 0; p < 2; p++)
        #pragma unroll
        for (int c = 0; c < 3; c++) acc[p][c] = 0ull;

    for (int kt = 0; kt < 32; kt++) {
        int k0 = kt*32;
        #pragma unroll
        for (int p = 0; p < 4; p++) {          // A: 16 rows x 32 k
            int ii = t + p*128;
            int r = ii >> 5, k = ii & 31;
            int kk = k0 + k;
            float v;
            if (kk < 256) v = g_att[((size_t)h*NN + (I0+r))*NN + kk];
            else          v = g_ec [((size_t)h*NN + (I0+r))*EE + kk - 256];
            Aat[k][r] = v;
        }
        #pragma unroll
        for (int p = 0; p < 6; p++) {          // B: 32 k x 24 float4, duplicated
            int i4 = t + p*128;
            int k = i4/24, f4 = (i4 - k*24)*4;
            int kk = k0 + k;
            float4 v;
            if (kk < 256) v = *(const float4*)(g_hv + ((size_t)h*NN + kk)*FF + f4);
            else          v = *(const float4*)(Wve + (size_t)(kk-256)*FF + f4);
            float2* d = (float2*)&Bvd[k][2*f4];
            d[0] = make_float2(v.x, v.x); d[1] = make_float2(v.y, v.y);
            d[2] = make_float2(v.z, v.z); d[3] = make_float2(v.w, v.w);
        }
        __syncthreads();
        #pragma unroll
        for (int k = 0; k < 32; k++) {
            ulonglong2 av = *(const ulonglong2*)&Aat[k][ty*4];
            ull b0 = *(const ull*)&Bvd[k][2*fx];
            ull b1 = *(const ull*)&Bvd[k][2*(fx+32)];
            ull b2 = *(const ull*)&Bvd[k][2*(fx+64)];
            ffma2(acc[0][0], av.x, b0); ffma2(acc[0][1], av.x, b1); ffma2(acc[0][2], av.x, b2);
            ffma2(acc[1][0], av.y, b0); ffma2(acc[1][1], av.y, b1); ffma2(acc[1][2], av.y, b2);
        }
        __syncthreads();
    }

    #pragma unroll
    for (int p = 0; p < 2; p++) {
        #pragma unroll
        for (int c = 0; c < 3; c++) {
            float2 u = unpack2(acc[p][c]);
            #pragma unroll
            for (int s = 0; s < 2; s++) {
                int n = I0 + ty*4 + p*2 + s;
                int col = h*96 + fx + c*32;
                float o = s ? u.y : u.x;
                o = o > 0.f ? o : (__expf(o) - 1.f);
                out[(size_t)n*2304 + 768*(l+1) + col] = o;
                g_cur[n*768 + col] = o;
            }
        }
    }
}

// ---------------- launch ----------------
extern "C" void kernel_launch(void* const* d_in, const int* in_sizes, int n_in,
                              void* d_out, int out_size) {
    const float* x   = (const float*)d_in[0];
    const int*   adj = (const int*)  d_in[1];
    const float* e   = (const float*)d_in[2];
    const float* Wq  = (const float*)d_in[3];
    const float* Wk  = (const float*)d_in[4];
    const float* Wv  = (const float*)d_in[5];
    const float* a   = (const float*)d_in[6];
    float* out = (float*)d_out;

    k_copy_x<<<(NN*DD + 255)/256, 256>>>(x, out);
    k_wk_a2<<<(LL*HH*EE*32 + 255)/256, 256>>>(Wk, a);
    k_se<<<512, 128>>>(e);

    for (int l = 0; l < LL; l++) {
        k_proj<<<dim3(24, 8), 256>>>(x, Wq, Wk, Wv, a, l);
        k_softmax<<<dim3(NN, HH), 256>>>(adj, l);
        k_ec<<<dim3(NN, 2), 96>>>(e);
        k_av<<<dim3(16, 8), 128>>>(Wv, out, l);
    }
}

// round 7
// speedup vs baseline: 1.0904x; 1.0904x over previous
#include <cuda_runtime.h>
#include <cstdint>

#define NN 256
#define DD 768
#define EE 768
#define FF 96
#define HH 8
#define LL 2
#define ALPHAV 0.2f
#define NEGV (-9000000000000000.0f)

typedef unsigned long long ull;

static __device__ __forceinline__ void ffma2(ull &d, ull a, ull b) {
    asm("fma.rn.f32x2 %0, %1, %2, %0;" : "+l"(d) : "l"(a), "l"(b));
}
static __device__ __forceinline__ float2 unpack2(ull v) {
    float2 r; asm("mov.b64 {%0, %1}, %2;" : "=f"(r.x), "=f"(r.y) : "l"(v)); return r;
}
static __device__ __forceinline__ ull dup2(float v) {
    ull r; asm("mov.b64 %0, {%1, %1};" : "=l"(r) : "f"(v)); return r;
}

// ---------------- device scratch ----------------
__device__ float g_wk_a2[LL*HH*EE];
__device__ float g_se[(size_t)LL*HH*NN*NN];
__device__ float g_hq[HH*NN*FF];
__device__ float g_hk[HH*NN*FF];
__device__ float g_hv[HH*NN*FF];
__device__ float g_sq[HH*NN];
__device__ float g_sk[HH*NN];
__device__ float g_att[HH*NN*NN];
__device__ __align__(16) float g_ec[HH*NN*EE];
__device__ float g_cur[NN*DD];

// ---------------- K0: copy x into out[:, 0:768] ----------------
__global__ void k_copy_x(const float* __restrict__ x, float* __restrict__ out) {
    int idx = blockIdx.x*blockDim.x + threadIdx.x;
    if (idx >= NN*DD) return;
    int n = idx / DD, c = idx - n*DD;
    out[(size_t)n*(3*DD) + c] = x[idx];
}

// ---------------- K1: wk_a2 ----------------
__global__ void k_wk_a2(const float* __restrict__ Wk, const float* __restrict__ a) {
    int gw   = (blockIdx.x*blockDim.x + threadIdx.x) >> 5;
    int lane = threadIdx.x & 31;
    if (gw >= LL*HH*EE) return;
    int lh = gw / EE;
    int d  = gw - lh*EE;
    const float* wrow = Wk + ((size_t)lh*(DD+EE) + DD + d)*FF;
    const float* arow = a + (size_t)lh*2*FF + FF;
    float s = 0.f;
    #pragma unroll
    for (int p = 0; p < 3; p++) s += wrow[lane + p*32] * arow[lane + p*32];
    #pragma unroll
    for (int o = 16; o; o >>= 1) s += __shfl_xor_sync(0xffffffffu, s, o);
    if (lane == 0) g_wk_a2[gw] = s;
}

// ---------------- K2: s_e = e_flat(65536x768) @ wk_a2^T(768x16) ----------------
__global__ __launch_bounds__(128) void k_se(const float* __restrict__ e) {
    __shared__ __align__(16) float As[32][132];
    __shared__ __align__(16) float Bd[32][34];
    int t  = threadIdx.x;
    int r0 = blockIdx.x * 128;
    int rg4 = (t & 31) * 4;
    int c0  = (t >> 5) * 4;
    int ar = t >> 3, ak = (t & 7) * 4;

    ull acc[2][4];
    #pragma unroll
    for (int p = 0; p < 2; p++)
        #pragma unroll
        for (int c = 0; c < 4; c++) acc[p][c] = 0ull;

    float4 pa[8];
    float  pbv[4];
    #pragma unroll
    for (int p = 0; p < 8; p++)
        pa[p] = *(const float4*)(e + (size_t)(r0 + ar + p*16)*EE + ak);
    #pragma unroll
    for (int p = 0; p < 4; p++) {
        int idx = t + p*128;
        pbv[p] = g_wk_a2[(idx >> 5)*EE + (idx & 31)];
    }

    for (int kt = 0; kt < 24; kt++) {
        #pragma unroll
        for (int p = 0; p < 8; p++) {
            int r = ar + p*16;
            As[ak+0][r] = pa[p].x; As[ak+1][r] = pa[p].y;
            As[ak+2][r] = pa[p].z; As[ak+3][r] = pa[p].w;
        }
        #pragma unroll
        for (int p = 0; p < 4; p++) {
            int idx = t + p*128;
            float v = pbv[p];
            *(float2*)&Bd[idx & 31][2*(idx >> 5)] = make_float2(v, v);
        }
        __syncthreads();
        if (kt < 23) {
            int k0 = (kt+1)*32;
            #pragma unroll
            for (int p = 0; p < 8; p++)
                pa[p] = *(const float4*)(e + (size_t)(r0 + ar + p*16)*EE + k0 + ak);
            #pragma unroll
            for (int p = 0; p < 4; p++) {
                int idx = t + p*128;
                pbv[p] = g_wk_a2[(idx >> 5)*EE + k0 + (idx & 31)];
            }
        }
        #pragma unroll
        for (int k = 0; k < 32; k++) {
            ulonglong2 av = *(const ulonglong2*)&As[k][rg4];
            #pragma unroll
            for (int cc = 0; cc < 4; cc++) {
                ull b = *(const ull*)&Bd[k][2*(c0+cc)];
                ffma2(acc[0][cc], av.x, b);
                ffma2(acc[1][cc], av.y, b);
            }
        }
        __syncthreads();
    }
    #pragma unroll
    for (int cc = 0; cc < 4; cc++) {
        int c = c0 + cc;
        #pragma unroll
        for (int p = 0; p < 2; p++) {
            float2 u = unpack2(acc[p][cc]);
            g_se[(size_t)c*65536 + r0 + rg4 + p*2 + 0] = u.x;
            g_se[(size_t)c*65536 + r0 + rg4 + p*2 + 1] = u.y;
        }
    }
}

// ---------------- K3: projections v3 — A-dup FFMA2, natural B, 128 threads ----------------
// grid (24, 8): mat = sel*8+h, 32-row tile. Thread: 4 rows x 6 cols (3 col-pairs).
__global__ __launch_bounds__(128) void k_proj(const float* __restrict__ x,
                                              const float* __restrict__ Wq,
                                              const float* __restrict__ Wk,
                                              const float* __restrict__ Wv,
                                              const float* __restrict__ a, int l) {
    const float* cur = l ? g_cur : x;
    int m = blockIdx.x, sel = m >> 3, h = m & 7;
    int lh = l*8 + h;
    int R0 = blockIdx.y * 32;
    const float* W = (sel == 0) ? Wq + (size_t)lh*DD*FF
                   : (sel == 1) ? Wk + (size_t)lh*(DD+EE)*FF
                   :              Wv + (size_t)lh*(DD+EE)*FF;
    __shared__ __align__(16) float Ad[32][64];   // [k][2*row] duplicated A, 256B rows
    __shared__ __align__(16) float Bs[32][96];   // [k][f] natural, 384B rows

    int t = threadIdx.x;
    int ty = t >> 4;          // 0..7 -> rows 4ty..4ty+3
    int fx = t & 15;          // col pairs at 2fx, 2fx+32, 2fx+64
    int ar = t >> 2, akq = (t & 3)*8;    // A loader: row ar, k=akq..akq+7

    ull acc[4][3];
    #pragma unroll
    for (int r = 0; r < 4; r++)
        #pragma unroll
        for (int c = 0; c < 3; c++) acc[r][c] = 0ull;

    const float* ap = cur + (size_t)(R0 + ar)*DD + akq;
    float4 pa0 = *(const float4*)(ap);
    float4 pa1 = *(const float4*)(ap + 4);
    float4 pb[6];
    #pragma unroll
    for (int p = 0; p < 6; p++) {
        int i4 = t + p*128;
        int k = i4/24, f4 = (i4 - k*24)*4;
        pb[p] = *(const float4*)(W + (size_t)k*FF + f4);
    }

    for (int kt = 0; kt < 24; kt++) {
        {
            float av[8] = {pa0.x,pa0.y,pa0.z,pa0.w, pa1.x,pa1.y,pa1.z,pa1.w};
            #pragma unroll
            for (int kk = 0; kk < 8; kk++)
                *(float2*)&Ad[akq+kk][2*ar] = make_float2(av[kk], av[kk]);
        }
        #pragma unroll
        for (int p = 0; p < 6; p++) {
            int i4 = t + p*128;
            int k = i4/24, f4 = (i4 - k*24)*4;
            *(float4*)&Bs[k][f4] = pb[p];
        }
        __syncthreads();
        if (kt < 23) {
            int k0 = (kt+1)*32;
            pa0 = *(const float4*)(ap + k0);
            pa1 = *(const float4*)(ap + k0 + 4);
            #pragma unroll
            for (int p = 0; p < 6; p++) {
                int i4 = t + p*128;
                int k = i4/24, f4 = (i4 - k*24)*4;
                pb[p] = *(const float4*)(W + (size_t)(k0+k)*FF + f4);
            }
        }
        #pragma unroll
        for (int k = 0; k < 32; k++) {
            ulonglong2 a01 = *(const ulonglong2*)&Ad[k][8*ty];      // rows 4ty,4ty+1 dup
            ulonglong2 a23 = *(const ulonglong2*)&Ad[k][8*ty + 4];  // rows 4ty+2,4ty+3 dup
            ull b0 = *(const ull*)&Bs[k][2*fx];
            ull b1 = *(const ull*)&Bs[k][2*fx + 32];
            ull b2 = *(const ull*)&Bs[k][2*fx + 64];
            ffma2(acc[0][0], a01.x, b0); ffma2(acc[0][1], a01.x, b1); ffma2(acc[0][2], a01.x, b2);
            ffma2(acc[1][0], a01.y, b0); ffma2(acc[1][1], a01.y, b1); ffma2(acc[1][2], a01.y, b2);
            ffma2(acc[2][0], a23.x, b0); ffma2(acc[2][1], a23.x, b1); ffma2(acc[2][2], a23.x, b2);
            ffma2(acc[3][0], a23.y, b0); ffma2(acc[3][1], a23.y, b1); ffma2(acc[3][2], a23.y, b2);
        }
        __syncthreads();
    }

    float* dst = (sel == 0) ? g_hq : (sel == 1) ? g_hk : g_hv;
    #pragma unroll
    for (int rr = 0; rr < 4; rr++) {
        int n = R0 + 4*ty + rr;
        #pragma unroll
        for (int c = 0; c < 3; c++) {
            float2 u = unpack2(acc[rr][c]);
            *(float2*)&dst[((size_t)h*NN + n)*FF + 2*fx + c*32] = u;
        }
    }
    if (sel < 2) {      // fused sq / sk
        const float* av = a + (size_t)lh*2*FF + sel*FF;
        float2 a0 = *(const float2*)&av[2*fx];
        float2 a1 = *(const float2*)&av[2*fx + 32];
        float2 a2 = *(const float2*)&av[2*fx + 64];
        #pragma unroll
        for (int rr = 0; rr < 4; rr++) {
            float2 u0 = unpack2(acc[rr][0]);
            float2 u1 = unpack2(acc[rr][1]);
            float2 u2 = unpack2(acc[rr][2]);
            float p = u0.x*a0.x + u0.y*a0.y + u1.x*a1.x + u1.y*a1.y + u2.x*a2.x + u2.y*a2.y;
            #pragma unroll
            for (int o = 8; o; o >>= 1) p += __shfl_xor_sync(0xffffffffu, p, o);
            if (fx == 0)
                (sel ? g_sk : g_sq)[h*NN + R0 + 4*ty + rr] = p;
        }
    }
}

// ---------------- K5: softmax ----------------
__global__ __launch_bounds__(256) void k_softmax(const int* __restrict__ adj, int l) {
    int i = blockIdx.x, h = blockIdx.y, j = threadIdx.x;
    int lh = l*8 + h;
    float sv = g_sq[h*NN + i] + g_sk[h*NN + j] + g_se[((size_t)lh*NN + i)*NN + j];
    sv = sv > 0.f ? sv : ALPHAV*sv;
    if (adj[i*NN + j] <= 0) sv = NEGV;

    __shared__ float red[8];
    int lane = j & 31, wid = j >> 5;
    float m = sv;
    #pragma unroll
    for (int o = 16; o; o >>= 1) m = fmaxf(m, __shfl_xor_sync(0xffffffffu, m, o));
    if (lane == 0) red[wid] = m;
    __syncthreads();
    float mx = red[0];
    #pragma unroll
    for (int p = 1; p < 8; p++) mx = fmaxf(mx, red[p]);
    __syncthreads();

    float ex = __expf(sv - mx);
    float s = ex;
    #pragma unroll
    for (int o = 16; o; o >>= 1) s += __shfl_xor_sync(0xffffffffu, s, o);
    if (lane == 0) red[wid] = s;
    __syncthreads();
    float tot = red[0];
    #pragma unroll
    for (int p = 1; p < 8; p++) tot += red[p];
    g_att[((size_t)h*NN + i)*NN + j] = ex * (1.0f / tot);
}

// ---------------- K6: ec v3 — FFMA2 paired over heads, att natural pairs ----------------
// grid (i, dhalf), 96 threads x 4 d-cols. Per j: 2 LDS.128 att (4 h-pairs), e dup'd by MOV.
__global__ __launch_bounds__(96) void k_ec(const float* __restrict__ e) {
    int i = blockIdx.x;
    int t = threadIdx.x;
    __shared__ __align__(16) float satt2[NN][8];   // [j][h], 8KB
    for (int idx = t; idx < HH*NN; idx += 96) {
        int h = idx >> 8, j = idx & 255;
        satt2[j][h] = g_att[(size_t)h*NN*NN + (size_t)i*NN + j];
    }
    __syncthreads();

    int d0 = blockIdx.y*384 + t*4;
    ull acc[4][4];    // [h-pair][d]
    #pragma unroll
    for (int hp = 0; hp < 4; hp++)
        #pragma unroll
        for (int d = 0; d < 4; d++) acc[hp][d] = 0ull;

    const float* ebase = e + (size_t)i*NN*EE + d0;
    #pragma unroll 1
    for (int j = 0; j < NN; j += 8) {
        float4 ev[8];
        #pragma unroll
        for (int u = 0; u < 8; u++)
            ev[u] = *(const float4*)(ebase + (size_t)(j+u)*EE);
        #pragma unroll
        for (int u = 0; u < 8; u++) {
            ulonglong2 ap0 = *(const ulonglong2*)&satt2[j+u][0];  // pairs h01, h23
            ulonglong2 ap1 = *(const ulonglong2*)&satt2[j+u][4];  // pairs h45, h67
            ull e0 = dup2(ev[u].x), e1 = dup2(ev[u].y);
            ull e2 = dup2(ev[u].z), e3 = dup2(ev[u].w);
            ffma2(acc[0][0], ap0.x, e0); ffma2(acc[0][1], ap0.x, e1);
            ffma2(acc[0][2], ap0.x, e2); ffma2(acc[0][3], ap0.x, e3);
            ffma2(acc[1][0], ap0.y, e0); ffma2(acc[1][1], ap0.y, e1);
            ffma2(acc[1][2], ap0.y, e2); ffma2(acc[1][3], ap0.y, e3);
            ffma2(acc[2][0], ap1.x, e0); ffma2(acc[2][1], ap1.x, e1);
            ffma2(acc[2][2], ap1.x, e2); ffma2(acc[2][3], ap1.x, e3);
            ffma2(acc[3][0], ap1.y, e0); ffma2(acc[3][1], ap1.y, e1);
            ffma2(acc[3][2], ap1.y, e2); ffma2(acc[3][3], ap1.y, e3);
        }
    }
    #pragma unroll
    for (int hp = 0; hp < 4; hp++) {
        float2 u0 = unpack2(acc[hp][0]);
        float2 u1 = unpack2(acc[hp][1]);
        float2 u2 = unpack2(acc[hp][2]);
        float2 u3 = unpack2(acc[hp][3]);
        float4 lo = make_float4(u0.x, u1.x, u2.x, u3.x);   // head 2*hp
        float4 hi = make_float4(u0.y, u1.y, u2.y, u3.y);   // head 2*hp+1
        *(float4*)(g_ec + ((size_t)((2*hp+0)*NN + i))*EE + d0) = lo;
        *(float4*)(g_ec + ((size_t)((2*hp+1)*NN + i))*EE + d0) = hi;
    }
}

// ---------------- K7: out = [att|ec] @ [hv;Wv_e], ELU. FFMA2 + dup B ----------------
__global__ __launch_bounds__(128) void k_av(const float* __restrict__ Wv,
                                            float* __restrict__ out, int l) {
    __shared__ __align__(16) float Aat[32][20];
    __shared__ __align__(16) float Bvd[32][192];
    int t  = threadIdx.x;
    int I0 = blockIdx.x*16, h = blockIdx.y;
    int ty = t >> 5, fx = t & 31;
    const float* Wve = Wv + ((size_t)(l*8+h)*(DD+EE) + DD)*FF;

    ull acc[2][3];
    #pragma unroll
    for (int p = 0; p < 2; p++)
        #pragma unroll
        for (int c = 0; c < 3; c++) acc[p][c] = 0ull;

    for (int kt = 0; kt < 32; kt++) {
        int k0 = kt*32;
        #pragma unroll
        for (int p = 0; p < 4; p++) {
            int ii = t + p*128;
            int r = ii >> 5, k = ii & 31;
            int kk = k0 + k;
            float v;
            if (kk < 256) v = g_att[((size_t)h*NN + (I0+r))*NN + kk];
            else          v = g_ec [((size_t)h*NN + (I0+r))*EE + kk - 256];
            Aat[k][r] = v;
        }
        #pragma unroll
        for (int p = 0; p < 6; p++) {
            int i4 = t + p*128;
            int k = i4/24, f4 = (i4 - k*24)*4;
            int kk = k0 + k;
            float4 v;
            if (kk < 256) v = *(const float4*)(g_hv + ((size_t)h*NN + kk)*FF + f4);
            else          v = *(const float4*)(Wve + (size_t)(kk-256)*FF + f4);
            float2* d = (float2*)&Bvd[k][2*f4];
            d[0] = make_float2(v.x, v.x); d[1] = make_float2(v.y, v.y);
            d[2] = make_float2(v.z, v.z); d[3] = make_float2(v.w, v.w);
        }
        __syncthreads();
        #pragma unroll
        for (int k = 0; k < 32; k++) {
            ulonglong2 av = *(const ulonglong2*)&Aat[k][ty*4];
            ull b0 = *(const ull*)&Bvd[k][2*fx];
            ull b1 = *(const ull*)&Bvd[k][2*(fx+32)];
            ull b2 = *(const ull*)&Bvd[k][2*(fx+64)];
            ffma2(acc[0][0], av.x, b0); ffma2(acc[0][1], av.x, b1); ffma2(acc[0][2], av.x, b2);
            ffma2(acc[1][0], av.y, b0); ffma2(acc[1][1], av.y, b1); ffma2(acc[1][2], av.y, b2);
        }
        __syncthreads();
    }

    #pragma unroll
    for (int p = 0; p < 2; p++) {
        #pragma unroll
        for (int c = 0; c < 3; c++) {
            float2 u = unpack2(acc[p][c]);
            #pragma unroll
            for (int s = 0; s < 2; s++) {
                int n = I0 + ty*4 + p*2 + s;
                int col = h*96 + fx + c*32;
                float o = s ? u.y : u.x;
                o = o > 0.f ? o : (__expf(o) - 1.f);
                out[(size_t)n*2304 + 768*(l+1) + col] = o;
                g_cur[n*768 + col] = o;
            }
        }
    }
}

// ---------------- launch ----------------
extern "C" void kernel_launch(void* const* d_in, const int* in_sizes, int n_in,
                              void* d_out, int out_size) {
    const float* x   = (const float*)d_in[0];
    const int*   adj = (const int*)  d_in[1];
    const float* e   = (const float*)d_in[2];
    const float* Wq  = (const float*)d_in[3];
    const float* Wk  = (const float*)d_in[4];
    const float* Wv  = (const float*)d_in[5];
    const float* a   = (const float*)d_in[6];
    float* out = (float*)d_out;

    k_copy_x<<<(NN*DD + 255)/256, 256>>>(x, out);
    k_wk_a2<<<(LL*HH*EE*32 + 255)/256, 256>>>(Wk, a);
    k_se<<<512, 128>>>(e);

    for (int l = 0; l < LL; l++) {
        k_proj<<<dim3(24, 8), 128>>>(x, Wq, Wk, Wv, a, l);
        k_softmax<<<dim3(NN, HH), 256>>>(adj, l);
        k_ec<<<dim3(NN, 2), 96>>>(e);
        k_av<<<dim3(16, 8), 128>>>(Wv, out, l);
    }
}

// round 10
// speedup vs baseline: 1.3492x; 1.2374x over previous
#include <cuda_runtime.h>
#include <cstdint>

#define NN 256
#define DD 768
#define EE 768
#define FF 96
#define HH 8
#define LL 2
#define ALPHAV 0.2f
#define NEGV (-9000000000000000.0f)

typedef unsigned long long ull;

static __device__ __forceinline__ void ffma2(ull &d, ull a, ull b) {
    asm("fma.rn.f32x2 %0, %1, %2, %0;" : "+l"(d) : "l"(a), "l"(b));
}
static __device__ __forceinline__ void fadd2(ull &d, ull a) {
    asm("add.rn.f32x2 %0, %0, %1;" : "+l"(d) : "l"(a));
}
static __device__ __forceinline__ float2 unpack2(ull v) {
    float2 r; asm("mov.b64 {%0, %1}, %2;" : "=f"(r.x), "=f"(r.y) : "l"(v)); return r;
}
static __device__ __forceinline__ ull dup2(float v) {
    ull r; asm("mov.b64 %0, {%1, %1};" : "=l"(r) : "f"(v)); return r;
}

// ---------------- device scratch ----------------
__device__ __align__(16) float g_wk_a2[LL*HH*EE];
__device__ __align__(16) float g_se[(size_t)LL*HH*NN*NN];
__device__ __align__(16) float g_hq[HH*NN*FF];
__device__ __align__(16) float g_hk[HH*NN*FF];
__device__ __align__(16) float g_hv[HH*NN*FF];
__device__ __align__(16) float g_sq[HH*NN];
__device__ __align__(16) float g_sk[HH*NN];
__device__ __align__(16) float g_att[HH*NN*NN];
__device__ __align__(16) float g_ec[HH*NN*EE];
__device__ __align__(16) float g_cur[NN*DD];

// ---------------- K0: copy x into out[:, 0:768] ----------------
__global__ void k_copy_x(const float* __restrict__ x, float* __restrict__ out) {
    int idx = blockIdx.x*blockDim.x + threadIdx.x;
    if (idx >= NN*DD) return;
    int n = idx / DD, c = idx - n*DD;
    out[(size_t)n*(3*DD) + c] = x[idx];
}

// ---------------- K1: wk_a2 ----------------
__global__ void k_wk_a2(const float* __restrict__ Wk, const float* __restrict__ a) {
    int gw   = (blockIdx.x*blockDim.x + threadIdx.x) >> 5;
    int lane = threadIdx.x & 31;
    if (gw >= LL*HH*EE) return;
    int lh = gw / EE;
    int d  = gw - lh*EE;
    const float* wrow = Wk + ((size_t)lh*(DD+EE) + DD + d)*FF;
    const float* arow = a + (size_t)lh*2*FF + FF;
    float s = 0.f;
    #pragma unroll
    for (int p = 0; p < 3; p++) s += wrow[lane + p*32] * arow[lane + p*32];
    #pragma unroll
    for (int o = 16; o; o >>= 1) s += __shfl_xor_sync(0xffffffffu, s, o);
    if (lane == 0) g_wk_a2[gw] = s;
}

// ---------------- K2: s_e = e_flat(65536x768) @ wk_a2^T(768x16) ----------------
__global__ __launch_bounds__(128) void k_se(const float* __restrict__ e) {
    __shared__ __align__(16) float As[32][132];
    __shared__ __align__(16) float Bd[32][34];
    int t  = threadIdx.x;
    int r0 = blockIdx.x * 128;
    int rg4 = (t & 31) * 4;
    int c0  = (t >> 5) * 4;
    int ar = t >> 3, ak = (t & 7) * 4;

    ull acc[2][4];
    #pragma unroll
    for (int p = 0; p < 2; p++)
        #pragma unroll
        for (int c = 0; c < 4; c++) acc[p][c] = 0ull;

    float4 pa[8];
    float  pbv[4];
    #pragma unroll
    for (int p = 0; p < 8; p++)
        pa[p] = *(const float4*)(e + (size_t)(r0 + ar + p*16)*EE + ak);
    #pragma unroll
    for (int p = 0; p < 4; p++) {
        int idx = t + p*128;
        pbv[p] = g_wk_a2[(idx >> 5)*EE + (idx & 31)];
    }

    for (int kt = 0; kt < 24; kt++) {
        #pragma unroll
        for (int p = 0; p < 8; p++) {
            int r = ar + p*16;
            As[ak+0][r] = pa[p].x; As[ak+1][r] = pa[p].y;
            As[ak+2][r] = pa[p].z; As[ak+3][r] = pa[p].w;
        }
        #pragma unroll
        for (int p = 0; p < 4; p++) {
            int idx = t + p*128;
            float v = pbv[p];
            *(float2*)&Bd[idx & 31][2*(idx >> 5)] = make_float2(v, v);
        }
        __syncthreads();
        if (kt < 23) {
            int k0 = (kt+1)*32;
            #pragma unroll
            for (int p = 0; p < 8; p++)
                pa[p] = *(const float4*)(e + (size_t)(r0 + ar + p*16)*EE + k0 + ak);
            #pragma unroll
            for (int p = 0; p < 4; p++) {
                int idx = t + p*128;
                pbv[p] = g_wk_a2[(idx >> 5)*EE + k0 + (idx & 31)];
            }
        }
        #pragma unroll
        for (int k = 0; k < 32; k++) {
            ulonglong2 av = *(const ulonglong2*)&As[k][rg4];
            #pragma unroll
            for (int cc = 0; cc < 4; cc++) {
                ull b = *(const ull*)&Bd[k][2*(c0+cc)];
                ffma2(acc[0][cc], av.x, b);
                ffma2(acc[1][cc], av.y, b);
            }
        }
        __syncthreads();
    }
    #pragma unroll
    for (int cc = 0; cc < 4; cc++) {
        int c = c0 + cc;
        #pragma unroll
        for (int p = 0; p < 2; p++) {
            float2 u = unpack2(acc[p][cc]);
            g_se[(size_t)c*65536 + r0 + rg4 + p*2 + 0] = u.x;
            g_se[(size_t)c*65536 + r0 + rg4 + p*2 + 1] = u.y;
        }
    }
}

// ---------------- K3: projections v4 — in-block K-split x2, A-dup FFMA2 ----------------
// grid (24, 8), 256 threads: warps 0-3 k in [0,384), warps 4-7 k in [384,768).
__global__ __launch_bounds__(256) void k_proj(const float* __restrict__ x,
                                              const float* __restrict__ Wq,
                                              const float* __restrict__ Wk,
                                              const float* __restrict__ Wv,
                                              const float* __restrict__ a, int l) {
    const float* cur = l ? g_cur : x;
    int m = blockIdx.x, sel = m >> 3, h = m & 7;
    int lh = l*8 + h;
    int R0 = blockIdx.y * 32;
    const float* W = (sel == 0) ? Wq + (size_t)lh*DD*FF
                   : (sel == 1) ? Wk + (size_t)lh*(DD+EE)*FF
                   :              Wv + (size_t)lh*(DD+EE)*FF;
    __shared__ __align__(16) float Ad[2][32][64];   // per-group [k][2*row] dup A (16KB)
    __shared__ __align__(16) float Bs[2][32][96];   // per-group [k][f] natural (24KB)

    int t  = threadIdx.x;
    int kg = t >> 7;             // k-group 0/1
    int t1 = t & 127;
    int kbase = kg * 384;
    int ty = t1 >> 4;            // rows 4ty..4ty+3
    int fx = t1 & 15;            // col pairs 2fx, 2fx+32, 2fx+64
    int ar = t1 >> 2, akq = (t1 & 3)*8;

    ull acc[4][3];
    #pragma unroll
    for (int r = 0; r < 4; r++)
        #pragma unroll
        for (int c = 0; c < 3; c++) acc[r][c] = 0ull;

    const float* ap = cur + (size_t)(R0 + ar)*DD + kbase + akq;
    const float* Wb = W + (size_t)kbase*FF;
    float4 pa0 = *(const float4*)(ap);
    float4 pa1 = *(const float4*)(ap + 4);
    float4 pb[6];
    #pragma unroll
    for (int p = 0; p < 6; p++) {
        int i4 = t1 + p*128;
        int k = i4/24, f4 = (i4 - k*24)*4;
        pb[p] = *(const float4*)(Wb + (size_t)k*FF + f4);
    }

    for (int kt = 0; kt < 12; kt++) {
        {
            float av[8] = {pa0.x,pa0.y,pa0.z,pa0.w, pa1.x,pa1.y,pa1.z,pa1.w};
            #pragma unroll
            for (int kk = 0; kk < 8; kk++)
                *(float2*)&Ad[kg][akq+kk][2*ar] = make_float2(av[kk], av[kk]);
        }
        #pragma unroll
        for (int p = 0; p < 6; p++) {
            int i4 = t1 + p*128;
            int k = i4/24, f4 = (i4 - k*24)*4;
            *(float4*)&Bs[kg][k][f4] = pb[p];
        }
        __syncthreads();
        if (kt < 11) {
            int k0 = (kt+1)*32;
            pa0 = *(const float4*)(ap + k0);
            pa1 = *(const float4*)(ap + k0 + 4);
            #pragma unroll
            for (int p = 0; p < 6; p++) {
                int i4 = t1 + p*128;
                int k = i4/24, f4 = (i4 - k*24)*4;
                pb[p] = *(const float4*)(Wb + (size_t)(k0+k)*FF + f4);
            }
        }
        #pragma unroll
        for (int k = 0; k < 32; k++) {
            ulonglong2 a01 = *(const ulonglong2*)&Ad[kg][k][8*ty];
            ulonglong2 a23 = *(const ulonglong2*)&Ad[kg][k][8*ty + 4];
            ull b0 = *(const ull*)&Bs[kg][k][2*fx];
            ull b1 = *(const ull*)&Bs[kg][k][2*fx + 32];
            ull b2 = *(const ull*)&Bs[kg][k][2*fx + 64];
            ffma2(acc[0][0], a01.x, b0); ffma2(acc[0][1], a01.x, b1); ffma2(acc[0][2], a01.x, b2);
            ffma2(acc[1][0], a01.y, b0); ffma2(acc[1][1], a01.y, b1); ffma2(acc[1][2], a01.y, b2);
            ffma2(acc[2][0], a23.x, b0); ffma2(acc[2][1], a23.x, b1); ffma2(acc[2][2], a23.x, b2);
            ffma2(acc[3][0], a23.y, b0); ffma2(acc[3][1], a23.y, b1); ffma2(acc[3][2], a23.y, b2);
        }
        __syncthreads();
    }

    // cross-group reduce via Bs[1] (needs 12KB, has 12KB)
    ull* R = (ull*)&Bs[1][0][0];
    if (kg == 1) {
        #pragma unroll
        for (int r = 0; r < 4; r++)
            #pragma unroll
            for (int c = 0; c < 3; c++)
                R[t1*12 + r*3 + c] = acc[r][c];
    }
    __syncthreads();
    if (kg == 0) {
        #pragma unroll
        for (int r = 0; r < 4; r++)
            #pragma unroll
            for (int c = 0; c < 3; c++)
                fadd2(acc[r][c], R[t1*12 + r*3 + c]);

        float* dst = (sel == 0) ? g_hq : (sel == 1) ? g_hk : g_hv;
        #pragma unroll
        for (int rr = 0; rr < 4; rr++) {
            int n = R0 + 4*ty + rr;
            #pragma unroll
            for (int c = 0; c < 3; c++) {
                float2 u = unpack2(acc[rr][c]);
                *(float2*)&dst[((size_t)h*NN + n)*FF + 2*fx + c*32] = u;
            }
        }
        if (sel < 2) {      // fused sq / sk
            const float* av = a + (size_t)lh*2*FF + sel*FF;
            float2 a0 = *(const float2*)&av[2*fx];
            float2 a1 = *(const float2*)&av[2*fx + 32];
            float2 a2 = *(const float2*)&av[2*fx + 64];
            #pragma unroll
            for (int rr = 0; rr < 4; rr++) {
                float2 u0 = unpack2(acc[rr][0]);
                float2 u1 = unpack2(acc[rr][1]);
                float2 u2 = unpack2(acc[rr][2]);
                float p = u0.x*a0.x + u0.y*a0.y + u1.x*a1.x + u1.y*a1.y + u2.x*a2.x + u2.y*a2.y;
                #pragma unroll
                for (int o = 8; o; o >>= 1) p += __shfl_xor_sync(0xffffffffu, p, o);
                if (fx == 0)
                    (sel ? g_sk : g_sq)[h*NN + R0 + 4*ty + rr] = p;
            }
        }
    }
}

// ---------------- K5: softmax ----------------
__global__ __launch_bounds__(256) void k_softmax(const int* __restrict__ adj, int l) {
    int i = blockIdx.x, h = blockIdx.y, j = threadIdx.x;
    int lh = l*8 + h;
    float sv = g_sq[h*NN + i] + g_sk[h*NN + j] + g_se[((size_t)lh*NN + i)*NN + j];
    sv = sv > 0.f ? sv : ALPHAV*sv;
    if (adj[i*NN + j] <= 0) sv = NEGV;

    __shared__ float red[8];
    int lane = j & 31, wid = j >> 5;
    float m = sv;
    #pragma unroll
    for (int o = 16; o; o >>= 1) m = fmaxf(m, __shfl_xor_sync(0xffffffffu, m, o));
    if (lane == 0) red[wid] = m;
    __syncthreads();
    float mx = red[0];
    #pragma unroll
    for (int p = 1; p < 8; p++) mx = fmaxf(mx, red[p]);
    __syncthreads();

    float ex = __expf(sv - mx);
    float s = ex;
    #pragma unroll
    for (int o = 16; o; o >>= 1) s += __shfl_xor_sync(0xffffffffu, s, o);
    if (lane == 0) red[wid] = s;
    __syncthreads();
    float tot = red[0];
    #pragma unroll
    for (int p = 1; p < 8; p++) tot += red[p];
    g_att[((size_t)h*NN + i)*NN + j] = ex * (1.0f / tot);
}

// ---------------- K6: ec v4 — head-paired FFMA2 + register ping-pong prefetch ----------------
__global__ __launch_bounds__(96) void k_ec(const float* __restrict__ e) {
    int i = blockIdx.x;
    int t = threadIdx.x;
    __shared__ __align__(16) float satt2[NN][8];   // [j][h]
    for (int idx = t; idx < HH*NN; idx += 96) {
        int h = idx >> 8, j = idx & 255;
        satt2[j][h] = g_att[(size_t)h*NN*NN + (size_t)i*NN + j];
    }
    __syncthreads();

    int d0 = blockIdx.y*384 + t*4;
    ull acc[4][4];
    #pragma unroll
    for (int hp = 0; hp < 4; hp++)
        #pragma unroll
        for (int d = 0; d < 4; d++) acc[hp][d] = 0ull;

    const float* ebase = e + (size_t)i*NN*EE + d0;

    float4 eva[8], evb[8];
    #pragma unroll
    for (int u = 0; u < 8; u++)
        eva[u] = *(const float4*)(ebase + (size_t)u*EE);

    #pragma unroll 1
    for (int j = 0; j < NN; j += 16) {
        #pragma unroll
        for (int u = 0; u < 8; u++)
            evb[u] = *(const float4*)(ebase + (size_t)(j+8+u)*EE);
        #pragma unroll
        for (int u = 0; u < 8; u++) {
            ulonglong2 ap0 = *(const ulonglong2*)&satt2[j+u][0];
            ulonglong2 ap1 = *(const ulonglong2*)&satt2[j+u][4];
            ull e0 = dup2(eva[u].x), e1 = dup2(eva[u].y);
            ull e2 = dup2(eva[u].z), e3 = dup2(eva[u].w);
            ffma2(acc[0][0], ap0.x, e0); ffma2(acc[0][1], ap0.x, e1);
            ffma2(acc[0][2], ap0.x, e2); ffma2(acc[0][3], ap0.x, e3);
            ffma2(acc[1][0], ap0.y, e0); ffma2(acc[1][1], ap0.y, e1);
            ffma2(acc[1][2], ap0.y, e2); ffma2(acc[1][3], ap0.y, e3);
            ffma2(acc[2][0], ap1.x, e0); ffma2(acc[2][1], ap1.x, e1);
            ffma2(acc[2][2], ap1.x, e2); ffma2(acc[2][3], ap1.x, e3);
            ffma2(acc[3][0], ap1.y, e0); ffma2(acc[3][1], ap1.y, e1);
            ffma2(acc[3][2], ap1.y, e2); ffma2(acc[3][3], ap1.y, e3);
        }
        if (j + 16 < NN) {
            #pragma unroll
            for (int u = 0; u < 8; u++)
                eva[u] = *(const float4*)(ebase + (size_t)(j+16+u)*EE);
        }
        #pragma unroll
        for (int u = 0; u < 8; u++) {
            ulonglong2 ap0 = *(const ulonglong2*)&satt2[j+8+u][0];
            ulonglong2 ap1 = *(const ulonglong2*)&satt2[j+8+u][4];
            ull e0 = dup2(evb[u].x), e1 = dup2(evb[u].y);
            ull e2 = dup2(evb[u].z), e3 = dup2(evb[u].w);
            ffma2(acc[0][0], ap0.x, e0); ffma2(acc[0][1], ap0.x, e1);
            ffma2(acc[0][2], ap0.x, e2); ffma2(acc[0][3], ap0.x, e3);
            ffma2(acc[1][0], ap0.y, e0); ffma2(acc[1][1], ap0.y, e1);
            ffma2(acc[1][2], ap0.y, e2); ffma2(acc[1][3], ap0.y, e3);
            ffma2(acc[2][0], ap1.x, e0); ffma2(acc[2][1], ap1.x, e1);
            ffma2(acc[2][2], ap1.x, e2); ffma2(acc[2][3], ap1.x, e3);
            ffma2(acc[3][0], ap1.y, e0); ffma2(acc[3][1], ap1.y, e1);
            ffma2(acc[3][2], ap1.y, e2); ffma2(acc[3][3], ap1.y, e3);
        }
    }
    #pragma unroll
    for (int hp = 0; hp < 4; hp++) {
        float2 u0 = unpack2(acc[hp][0]);
        float2 u1 = unpack2(acc[hp][1]);
        float2 u2 = unpack2(acc[hp][2]);
        float2 u3 = unpack2(acc[hp][3]);
        float4 lo = make_float4(u0.x, u1.x, u2.x, u3.x);
        float4 hi = make_float4(u0.y, u1.y, u2.y, u3.y);
        *(float4*)(g_ec + ((size_t)((2*hp+0)*NN + i))*EE + d0) = lo;
        *(float4*)(g_ec + ((size_t)((2*hp+1)*NN + i))*EE + d0) = hi;
    }
}

// ---------------- K7: out = [att|ec] @ [hv;Wv_e], ELU. K-split x2, A-dup, natural B ----------------
// grid (32, 8), 256 threads: group 0 k in [0,512), group 1 k in [512,1024).
// 128 threads/group = 8 rows x 16 col-pair lanes; thread: 1 row x 3 col-pairs.
__global__ __launch_bounds__(256) void k_av(const float* __restrict__ Wv,
                                            float* __restrict__ out, int l) {
    __shared__ __align__(16) float Ad[2][32][16];    // [grp][k][2*row] dup A (4KB)
    __shared__ __align__(16) float Bs[2][32][96];    // [grp][k][f] natural (24KB)
    int t  = threadIdx.x;
    int kg = t >> 7;
    int t1 = t & 127;
    int kbase = kg * 512;
    int I0 = blockIdx.x*8, h = blockIdx.y;
    int ty = t1 >> 4;            // row 0..7
    int fx = t1 & 15;            // col pairs 2fx, 2fx+32, 2fx+64
    const float* Wve = Wv + ((size_t)(l*8+h)*(DD+EE) + DD)*FF;

    ull acc[3] = {0ull, 0ull, 0ull};

    for (int kt = 0; kt < 16; kt++) {
        int k0 = kbase + kt*32;
        #pragma unroll
        for (int p = 0; p < 2; p++) {          // A: 8 rows x 32 k, dup'd
            int ii = t1 + p*128;
            int r = ii >> 5, k = ii & 31;
            int kk = k0 + k;
            float v;
            if (kk < 256) v = g_att[((size_t)h*NN + (I0+r))*NN + kk];
            else          v = g_ec [((size_t)h*NN + (I0+r))*EE + kk - 256];
            *(float2*)&Ad[kg][k][2*r] = make_float2(v, v);
        }
        #pragma unroll
        for (int p = 0; p < 6; p++) {          // B: 32 k x 24 float4, natural
            int i4 = t1 + p*128;
            int k = i4/24, f4 = (i4 - k*24)*4;
            int kk = k0 + k;
            float4 v;
            if (kk < 256) v = *(const float4*)(g_hv + ((size_t)h*NN + kk)*FF + f4);
            else          v = *(const float4*)(Wve + (size_t)(kk-256)*FF + f4);
            *(float4*)&Bs[kg][k][f4] = v;
        }
        __syncthreads();
        #pragma unroll
        for (int k = 0; k < 32; k++) {
            ull av = *(const ull*)&Ad[kg][k][2*ty];
            ull b0 = *(const ull*)&Bs[kg][k][2*fx];
            ull b1 = *(const ull*)&Bs[kg][k][2*fx + 32];
            ull b2 = *(const ull*)&Bs[kg][k][2*fx + 64];
            ffma2(acc[0], av, b0); ffma2(acc[1], av, b1); ffma2(acc[2], av, b2);
        }
        __syncthreads();
    }

    // cross-group reduce via Bs[1] (needs 3KB of 12KB)
    ull* R = (ull*)&Bs[1][0][0];
    if (kg == 1) {
        #pragma unroll
        for (int c = 0; c < 3; c++) R[t1*3 + c] = acc[c];
    }
    __syncthreads();
    if (kg == 0) {
        #pragma unroll
        for (int c = 0; c < 3; c++) fadd2(acc[c], R[t1*3 + c]);
        int n = I0 + ty;
        #pragma unroll
        for (int c = 0; c < 3; c++) {
            float2 u = unpack2(acc[c]);
            #pragma unroll
            for (int s = 0; s < 2; s++) {
                int col = h*96 + 2*fx + c*32 + s;
                float o = s ? u.y : u.x;
                o = o > 0.f ? o : (__expf(o) - 1.f);
                out[(size_t)n*2304 + 768*(l+1) + col] = o;
                g_cur[n*768 + col] = o;
            }
        }
    }
}

// ---------------- launch ----------------
extern "C" void kernel_launch(void* const* d_in, const int* in_sizes, int n_in,
                              void* d_out, int out_size) {
    const float* x   = (const float*)d_in[0];
    const int*   adj = (const int*)  d_in[1];
    const float* e   = (const float*)d_in[2];
    const float* Wq  = (const float*)d_in[3];
    const float* Wk  = (const float*)d_in[4];
    const float* Wv  = (const float*)d_in[5];
    const float* a   = (const float*)d_in[6];
    float* out = (float*)d_out;

    k_copy_x<<<(NN*DD + 255)/256, 256>>>(x, out);
    k_wk_a2<<<(LL*HH*EE*32 + 255)/256, 256>>>(Wk, a);
    k_se<<<512, 128>>>(e);

    for (int l = 0; l < LL; l++) {
        k_proj<<<dim3(24, 8), 256>>>(x, Wq, Wk, Wv, a, l);
        k_softmax<<<dim3(NN, HH), 256>>>(adj, l);
        k_ec<<<dim3(NN, 2), 96>>>(e);
        k_av<<<dim3(32, 8), 256>>>(Wv, out, l);
    }
}